// round 5
// baseline (speedup 1.0000x reference)
#include <cuda_runtime.h>
#include <cuda_bf16.h>
#include <mma.h>

using namespace nvcuda;

#define BB 2
#define SS 2048
#define DD 512
#define HH 8
#define HDIM 64
#define KROUTE 64

// ---------------------------------------------------------------------------
// Scratch (device globals; no allocation allowed)
// ---------------------------------------------------------------------------
__device__ float g_q[BB * HH * SS * HDIM];
__device__ float g_k[BB * HH * SS * HDIM];
__device__ float g_v[BB * HH * SS * HDIM];

__device__ __nv_bfloat16 gx_hi[BB * SS * DD];
__device__ __nv_bfloat16 gx_lo[BB * SS * DD];
__device__ __nv_bfloat16 gw1_hi[DD * 3 * DD];
__device__ __nv_bfloat16 gw1_lo[DD * 3 * DD];
__device__ __nv_bfloat16 gw2_hi[DD * DD];
__device__ __nv_bfloat16 gw2_lo[DD * DD];
__device__ __nv_bfloat16 gat_hi[BB * SS * DD];
__device__ __nv_bfloat16 gat_lo[BB * SS * DD];

// ---------------------------------------------------------------------------
__device__ __forceinline__ void cp16(void* d, const void* s)
{
    unsigned ds = (unsigned)__cvta_generic_to_shared(d);
    asm volatile("cp.async.cg.shared.global [%0], [%1], 16;" :: "r"(ds), "l"(s));
}

// ---------------------------------------------------------------------------
// fp32 -> bf16 hi/lo split conversion (vectorized float4)
// ---------------------------------------------------------------------------
__global__ __launch_bounds__(256) void cvt_k(
    const float4* __restrict__ src,
    __nv_bfloat162* __restrict__ hi,
    __nv_bfloat162* __restrict__ lo, int n4)
{
    int i = blockIdx.x * 256 + threadIdx.x;
    if (i >= n4) return;
    float4 v = src[i];
    __nv_bfloat16 h0 = __float2bfloat16(v.x);
    __nv_bfloat16 h1 = __float2bfloat16(v.y);
    __nv_bfloat16 h2 = __float2bfloat16(v.z);
    __nv_bfloat16 h3 = __float2bfloat16(v.w);
    hi[2 * i + 0] = __halves2bfloat162(h0, h1);
    hi[2 * i + 1] = __halves2bfloat162(h2, h3);
    __nv_bfloat16 l0 = __float2bfloat16(v.x - __bfloat162float(h0));
    __nv_bfloat16 l1 = __float2bfloat16(v.y - __bfloat162float(h1));
    __nv_bfloat16 l2 = __float2bfloat16(v.z - __bfloat162float(h2));
    __nv_bfloat16 l3 = __float2bfloat16(v.w - __bfloat162float(h3));
    lo[2 * i + 0] = __halves2bfloat162(l0, l1);
    lo[2 * i + 1] = __halves2bfloat162(l2, l3);
}

// ---------------------------------------------------------------------------
// Tensor-core GEMM, bf16 hi/lo x3 split. 64x128x32 tile, 2-stage cp.async,
// 3 CTAs/SM (small tiles kill wave quantization). 8 warps: 2(m) x 4(n),
// warp tile 32x32 = 2x2 wmma frags.
// ---------------------------------------------------------------------------
template <int MODE>
__global__ __launch_bounds__(256, 3) void gemm_bf16(
    const __nv_bfloat16* __restrict__ Ahi, const __nv_bfloat16* __restrict__ Alo,
    const __nv_bfloat16* __restrict__ Bhi, const __nv_bfloat16* __restrict__ Blo,
    const float* __restrict__ bias, float* __restrict__ C,
    int M, int N, int Kd)
{
    extern __shared__ __align__(16) char smem[];
    constexpr int BM = 64, BN = 128, BK = 32;
    constexpr int LDA = BK + 8;    // 40
    constexpr int LDB = BN + 8;    // 136
    constexpr int LDS_ = BN + 4;   // 132 (epilogue staging, floats)
    constexpr int A_SZ = BM * LDA;                 // 2560 bf16
    constexpr int B_SZ = BK * LDB;                 // 4352 bf16
    constexpr int STG  = 2 * A_SZ + 2 * B_SZ;      // 13824 elems / stage

    __nv_bfloat16* base = (__nv_bfloat16*)smem;
    float* stagef = (float*)smem;   // union, reused after k-loop

    const int tid = threadIdx.x;
    const int wid = tid >> 5;
    const int wm = wid & 1;    // 2 m-warps
    const int wn = wid >> 1;   // 4 n-warps

    const size_t aBase = (size_t)blockIdx.y * BM * Kd;
    const int nBase = blockIdx.x * BN;
    const int nK = Kd / BK;

    wmma::fragment<wmma::accumulator, 16, 16, 16, float> acc[2][2];
    #pragma unroll
    for (int mi = 0; mi < 2; mi++)
        #pragma unroll
        for (int ni = 0; ni < 2; ni++) wmma::fill_fragment(acc[mi][ni], 0.0f);

    auto prefetch = [&](int ks, int st) {
        const int k0 = ks * BK;
        __nv_bfloat16* sAh = base + st * STG;
        __nv_bfloat16* sAl = sAh + A_SZ;
        __nv_bfloat16* sBh = sAl + A_SZ;
        __nv_bfloat16* sBl = sBh + B_SZ;
        // A: 64x32 = 256 16B-chunks (1/thread for hi, 1 for lo)
        {
            const int rA = tid >> 2, cA = (tid & 3) * 8;
            const size_t aoff = aBase + (size_t)rA * Kd + k0 + cA;
            cp16(&sAh[rA * LDA + cA], Ahi + aoff);
            cp16(&sAl[rA * LDA + cA], Alo + aoff);
        }
        // B: 32x128 = 512 chunks (2/thread each for hi, lo)
        #pragma unroll
        for (int i = 0; i < 2; i++) {
            const int c = tid + 256 * i;
            const int rB = c >> 4, cB = (c & 15) * 8;
            const size_t boff = (size_t)(k0 + rB) * N + nBase + cB;
            cp16(&sBh[rB * LDB + cB], Bhi + boff);
            cp16(&sBl[rB * LDB + cB], Blo + boff);
        }
        asm volatile("cp.async.commit_group;");
    };

    prefetch(0, 0);

    for (int ks = 0; ks < nK; ks++) {
        if (ks + 1 < nK) {
            prefetch(ks + 1, (ks + 1) & 1);
            asm volatile("cp.async.wait_group 1;");
        } else {
            asm volatile("cp.async.wait_group 0;");
        }
        __syncthreads();

        const int st = ks & 1;
        const __nv_bfloat16* sAh = base + st * STG;
        const __nv_bfloat16* sAl = sAh + A_SZ;
        const __nv_bfloat16* sBh = sAl + A_SZ;
        const __nv_bfloat16* sBl = sBh + B_SZ;

        #pragma unroll
        for (int kk = 0; kk < BK; kk += 16) {
            wmma::fragment<wmma::matrix_a, 16, 16, 16, __nv_bfloat16, wmma::row_major> ah[2], al[2];
            #pragma unroll
            for (int mi = 0; mi < 2; mi++) {
                wmma::load_matrix_sync(ah[mi], sAh + (wm * 32 + mi * 16) * LDA + kk, LDA);
                wmma::load_matrix_sync(al[mi], sAl + (wm * 32 + mi * 16) * LDA + kk, LDA);
            }
            #pragma unroll
            for (int ni = 0; ni < 2; ni++) {
                wmma::fragment<wmma::matrix_b, 16, 16, 16, __nv_bfloat16, wmma::row_major> bh, bl;
                wmma::load_matrix_sync(bh, sBh + kk * LDB + wn * 32 + ni * 16, LDB);
                wmma::load_matrix_sync(bl, sBl + kk * LDB + wn * 32 + ni * 16, LDB);
                #pragma unroll
                for (int mi = 0; mi < 2; mi++) {
                    wmma::mma_sync(acc[mi][ni], ah[mi], bh, acc[mi][ni]);
                    wmma::mma_sync(acc[mi][ni], ah[mi], bl, acc[mi][ni]);
                    wmma::mma_sync(acc[mi][ni], al[mi], bh, acc[mi][ni]);
                }
            }
        }
        __syncthreads();
    }

    // Epilogue: stage full 64x128 tile (33.8 KB < stage smem)
    #pragma unroll
    for (int mi = 0; mi < 2; mi++)
        #pragma unroll
        for (int ni = 0; ni < 2; ni++)
            wmma::store_matrix_sync(
                stagef + (wm * 32 + mi * 16) * LDS_ + wn * 32 + ni * 16,
                acc[mi][ni], LDS_, wmma::mem_row_major);
    __syncthreads();

    #pragma unroll 4
    for (int i = 0; i < (BM * BN) / 256; i++) {
        const int flat = i * 256 + tid;
        const int r = flat >> 7;
        const int c = flat & 127;
        const int n = nBase + c;
        const float v = stagef[r * LDS_ + c] + __ldg(&bias[n]);
        const int m = blockIdx.y * BM + r;
        if (MODE == 0) {
            C[(size_t)m * N + n] = v;
        } else {
            const int b = m >> 11;
            const int s = m & 2047;
            const int c3 = n >> 9;
            const int h = (n >> 6) & 7;
            const int d = n & 63;
            float* dst = (c3 == 0) ? g_q : (c3 == 1) ? g_k : g_v;
            dst[(((size_t)b * HH + h) * SS + s) * HDIM + d] = v;
        }
    }
}

// ---------------------------------------------------------------------------
// Routed attention v5: all 4 of the warp's queries in ONE pass (8 independent
// LDG.128 in flight). 8-lane groups own one route per query per iter.
// ---------------------------------------------------------------------------
__global__ __launch_bounds__(256) void attn_k(const int* __restrict__ routes)
{
    const unsigned FULL = 0xffffffffu;
    const int lane = threadIdx.x & 31;
    const int warp = threadIdx.x >> 5;
    const int chunks = SS / 32;
    const int bh = blockIdx.x / chunks;
    const int sc = blockIdx.x % chunks;
    const int b = bh >> 3, h = bh & 7;
    const int sub = lane & 7;     // 8-float slice of the 64-dim row
    const int grp = lane >> 3;    // 0..3: route group

    const float* Qb = g_q + (size_t)bh * SS * HDIM;
    const float* Kb = g_k + (size_t)bh * SS * HDIM;
    const float* Vb = g_v + (size_t)bh * SS * HDIM;

    const int s_base = sc * 32 + warp * 4;

    float4 qa[4], qb4[4];
    int rlo[4], rhi[4];
    #pragma unroll
    for (int q = 0; q < 4; q++) {
        const float4* qp = (const float4*)(Qb + (size_t)(s_base + q) * HDIM + sub * 8);
        qa[q] = qp[0];
        qb4[q] = qp[1];
        rlo[q] = routes[(s_base + q) * KROUTE + lane];
        rhi[q] = routes[(s_base + q) * KROUTE + 32 + lane];
    }

    float slo[4] = {0.f, 0.f, 0.f, 0.f};
    float shi[4] = {0.f, 0.f, 0.f, 0.f};

    #pragma unroll
    for (int t = 0; t < 16; t++) {
        const int kk31 = (t * 4 + grp) & 31;
        float p[4];
        #pragma unroll
        for (int q = 0; q < 4; q++) {
            const int r = __shfl_sync(FULL, (t < 8) ? rlo[q] : rhi[q], kk31);
            const float4* kp = (const float4*)(Kb + (size_t)r * HDIM + sub * 8);
            const float4 ka = kp[0], kb = kp[1];
            float pv = ka.x * qa[q].x;
            pv = fmaf(ka.y, qa[q].y, pv);
            pv = fmaf(ka.z, qa[q].z, pv);
            pv = fmaf(ka.w, qa[q].w, pv);
            pv = fmaf(kb.x, qb4[q].x, pv);
            pv = fmaf(kb.y, qb4[q].y, pv);
            pv = fmaf(kb.z, qb4[q].z, pv);
            pv = fmaf(kb.w, qb4[q].w, pv);
            p[q] = pv;
        }
        #pragma unroll
        for (int o = 1; o <= 4; o <<= 1)
            #pragma unroll
            for (int q = 0; q < 4; q++)
                p[q] += __shfl_xor_sync(FULL, p[q], o);
        #pragma unroll
        for (int q = 0; q < 4; q++) {
            const float v = __shfl_sync(FULL, p[q], (lane & 3) * 8);
            if ((lane >> 2) == t)     slo[q] = v;
            if ((lane >> 2) + 8 == t) shi[q] = v;
        }
    }

    float wlo[4], whi[4];
    #pragma unroll
    for (int q = 0; q < 4; q++) {
        slo[q] *= 0.125f;
        shi[q] *= 0.125f;
    }
    {
        float mx[4];
        #pragma unroll
        for (int q = 0; q < 4; q++) mx[q] = fmaxf(slo[q], shi[q]);
        #pragma unroll
        for (int o = 16; o; o >>= 1)
            #pragma unroll
            for (int q = 0; q < 4; q++)
                mx[q] = fmaxf(mx[q], __shfl_xor_sync(FULL, mx[q], o));
        float sum[4];
        #pragma unroll
        for (int q = 0; q < 4; q++) {
            wlo[q] = __expf(slo[q] - mx[q]);
            whi[q] = __expf(shi[q] - mx[q]);
            sum[q] = wlo[q] + whi[q];
        }
        #pragma unroll
        for (int o = 16; o; o >>= 1)
            #pragma unroll
            for (int q = 0; q < 4; q++)
                sum[q] += __shfl_xor_sync(FULL, sum[q], o);
        #pragma unroll
        for (int q = 0; q < 4; q++) {
            const float inv = __fdividef(1.f, sum[q]);
            wlo[q] *= inv;
            whi[q] *= inv;
        }
    }

    // AV: 4 routes/iter per query, 4 queries interleaved
    float4 aa[4], ab[4];
    #pragma unroll
    for (int q = 0; q < 4; q++) {
        aa[q] = make_float4(0.f, 0.f, 0.f, 0.f);
        ab[q] = make_float4(0.f, 0.f, 0.f, 0.f);
    }
    #pragma unroll
    for (int t = 0; t < 16; t++) {
        const int kk31 = (t * 4 + grp) & 31;
        #pragma unroll
        for (int q = 0; q < 4; q++) {
            const int r = __shfl_sync(FULL, (t < 8) ? rlo[q] : rhi[q], kk31);
            const float w = __shfl_sync(FULL, (t < 8) ? wlo[q] : whi[q], kk31);
            const float4* vp = (const float4*)(Vb + (size_t)r * HDIM + sub * 8);
            const float4 va = vp[0], vb = vp[1];
            aa[q].x = fmaf(w, va.x, aa[q].x);
            aa[q].y = fmaf(w, va.y, aa[q].y);
            aa[q].z = fmaf(w, va.z, aa[q].z);
            aa[q].w = fmaf(w, va.w, aa[q].w);
            ab[q].x = fmaf(w, vb.x, ab[q].x);
            ab[q].y = fmaf(w, vb.y, ab[q].y);
            ab[q].z = fmaf(w, vb.z, ab[q].z);
            ab[q].w = fmaf(w, vb.w, ab[q].w);
        }
    }
    // reduce across the 4 groups (lanes with equal sub)
    #pragma unroll
    for (int o = 8; o <= 16; o <<= 1)
        #pragma unroll
        for (int q = 0; q < 4; q++) {
            aa[q].x += __shfl_xor_sync(FULL, aa[q].x, o);
            aa[q].y += __shfl_xor_sync(FULL, aa[q].y, o);
            aa[q].z += __shfl_xor_sync(FULL, aa[q].z, o);
            aa[q].w += __shfl_xor_sync(FULL, aa[q].w, o);
            ab[q].x += __shfl_xor_sync(FULL, ab[q].x, o);
            ab[q].y += __shfl_xor_sync(FULL, ab[q].y, o);
            ab[q].z += __shfl_xor_sync(FULL, ab[q].z, o);
            ab[q].w += __shfl_xor_sync(FULL, ab[q].w, o);
        }

    if (lane < 8) {
        #pragma unroll
        for (int q = 0; q < 4; q++) {
            const int s = s_base + q;
            const size_t off = ((size_t)(b * SS + s)) * DD + h * HDIM + sub * 8;
            float f[8] = {aa[q].x, aa[q].y, aa[q].z, aa[q].w,
                          ab[q].x, ab[q].y, ab[q].z, ab[q].w};
            __nv_bfloat162 hp[4], lp[4];
            #pragma unroll
            for (int j = 0; j < 4; j++) {
                __nv_bfloat16 h0 = __float2bfloat16(f[2 * j]);
                __nv_bfloat16 h1 = __float2bfloat16(f[2 * j + 1]);
                hp[j] = __halves2bfloat162(h0, h1);
                __nv_bfloat16 l0 = __float2bfloat16(f[2 * j] - __bfloat162float(h0));
                __nv_bfloat16 l1 = __float2bfloat16(f[2 * j + 1] - __bfloat162float(h1));
                lp[j] = __halves2bfloat162(l0, l1);
            }
            *(uint4*)&gat_hi[off] = *(uint4*)hp;
            *(uint4*)&gat_lo[off] = *(uint4*)lp;
        }
    }
}

// ---------------------------------------------------------------------------
extern "C" void kernel_launch(void* const* d_in, const int* in_sizes, int n_in,
                              void* d_out, int out_size)
{
    const float* x      = (const float*)d_in[0];
    const float* Wqkv   = (const float*)d_in[1];
    const float* bqkv   = (const float*)d_in[2];
    const float* Wout   = (const float*)d_in[3];
    const float* bout   = (const float*)d_in[4];
    const int*   routes = (const int*)d_in[5];
    float* out = (float*)d_out;

    __nv_bfloat16 *xh, *xl, *w1h, *w1l, *w2h, *w2l, *ath, *atl;
    cudaGetSymbolAddress((void**)&xh,  gx_hi);
    cudaGetSymbolAddress((void**)&xl,  gx_lo);
    cudaGetSymbolAddress((void**)&w1h, gw1_hi);
    cudaGetSymbolAddress((void**)&w1l, gw1_lo);
    cudaGetSymbolAddress((void**)&w2h, gw2_hi);
    cudaGetSymbolAddress((void**)&w2l, gw2_lo);
    cudaGetSymbolAddress((void**)&ath, gat_hi);
    cudaGetSymbolAddress((void**)&atl, gat_lo);

    // smem: 2 stages x (2 x 64*40 + 2 x 32*136) bf16 = 55,296 bytes
    constexpr int SMEM_BYTES = 2 * (2 * 64 * 40 + 2 * 32 * 136) * 2;
    cudaFuncSetAttribute(gemm_bf16<0>, cudaFuncAttributeMaxDynamicSharedMemorySize, SMEM_BYTES);
    cudaFuncSetAttribute(gemm_bf16<1>, cudaFuncAttributeMaxDynamicSharedMemorySize, SMEM_BYTES);

    // 1) split-precision conversions
    {
        int n4 = (BB * SS * DD) / 4;
        cvt_k<<<(n4 + 255) / 256, 256>>>((const float4*)x, (__nv_bfloat162*)xh, (__nv_bfloat162*)xl, n4);
        n4 = (DD * 3 * DD) / 4;
        cvt_k<<<(n4 + 255) / 256, 256>>>((const float4*)Wqkv, (__nv_bfloat162*)w1h, (__nv_bfloat162*)w1l, n4);
        n4 = (DD * DD) / 4;
        cvt_k<<<(n4 + 255) / 256, 256>>>((const float4*)Wout, (__nv_bfloat162*)w2h, (__nv_bfloat162*)w2l, n4);
    }

    // 2) QKV GEMM + head-scatter epilogue: grid (12, 64) = 768 CTAs
    gemm_bf16<1><<<dim3(3 * DD / 128, (BB * SS) / 64), 256, SMEM_BYTES>>>(
        xh, xl, w1h, w1l, bqkv, nullptr, BB * SS, 3 * DD, DD);

    // 3) routed attention
    attn_k<<<BB * HH * (SS / 32), 256>>>(routes);

    // 4) out projection: grid (4, 64) = 256 CTAs -> single wave
    gemm_bf16<0><<<dim3(DD / 128, (BB * SS) / 64), 256, SMEM_BYTES>>>(
        ath, atl, w2h, w2l, bout, out, BB * SS, DD, DD);
}

// round 8
// speedup vs baseline: 1.5634x; 1.5634x over previous
#include <cuda_runtime.h>
#include <cuda_fp16.h>
#include <mma.h>
#include <cstdint>
#include <cstddef>

using namespace nvcuda;

#define BB 2
#define SS 2048
#define DD 512
#define HH 8
#define HDIM 64
#define KROUTE 64

// ---------------------------------------------------------------------------
// Scratch (device globals; no allocation allowed)
// ---------------------------------------------------------------------------
__device__ float g_q[BB * HH * SS * HDIM];
__device__ float g_k[BB * HH * SS * HDIM];
__device__ float g_v[BB * HH * SS * HDIM];

__device__ __align__(16) __half gx[BB * SS * DD];
__device__ __align__(16) __half gw1[DD * 3 * DD];
__device__ __align__(16) __half gw2[DD * DD];
__device__ __align__(16) __half gat[BB * SS * DD];

// ---------------------------------------------------------------------------
__device__ __forceinline__ void cp16(void* d, const void* s)
{
    unsigned ds = (unsigned)__cvta_generic_to_shared(d);
    asm volatile("cp.async.cg.shared.global [%0], [%1], 16;" :: "r"(ds), "l"(s));
}

// ---------------------------------------------------------------------------
// fp32 -> fp16 conversion (vectorized float4 -> 2x half2)
// ---------------------------------------------------------------------------
__global__ __launch_bounds__(256) void cvt_k(
    const float4* __restrict__ src, __half2* __restrict__ dst, int n4)
{
    int i = blockIdx.x * 256 + threadIdx.x;
    if (i >= n4) return;
    float4 v = src[i];
    dst[2 * i + 0] = __floats2half2_rn(v.x, v.y);
    dst[2 * i + 1] = __floats2half2_rn(v.z, v.w);
}

// ---------------------------------------------------------------------------
// Tensor-core GEMM, single fp16 term, fp32 accumulate. 128x128x32 tile,
// 2-stage cp.async double buffering, 2 CTAs/SM. 8 warps: 4(m) x 2(n);
// warp tile 32x64 = 2x4 wmma 16x16x16 frags.
//   MODE 0: dense store   MODE 1: scatter to g_q/g_k/g_v (head reshuffle)
// ---------------------------------------------------------------------------
template <int MODE>
__global__ __launch_bounds__(256, 2) void gemm_fp16(
    const __half* __restrict__ A, const __half* __restrict__ B,
    const float* __restrict__ bias, float* __restrict__ C,
    int M, int N, int Kd)
{
    extern __shared__ __align__(16) char smem[];
    constexpr int BM = 128, BN = 128, BK = 32;
    constexpr int LDA = BK + 8;    // 40
    constexpr int LDB = BN + 8;    // 136
    constexpr int LDS_ = BN + 4;   // 132 floats, epilogue staging
    constexpr int A_SZ = BM * LDA; // 5120 halves
    constexpr int B_SZ = BK * LDB; // 4352 halves
    constexpr int STG = A_SZ + B_SZ;

    __half* base = (__half*)smem;
    float* stagef = (float*)smem;  // union, reused after k-loop

    const int tid = threadIdx.x;
    const int wid = tid >> 5;
    const int wm = wid & 3;
    const int wn = wid >> 2;

    const size_t aBase = (size_t)blockIdx.y * BM * Kd;
    const int nBase = blockIdx.x * BN;
    const int nK = Kd / BK;

    wmma::fragment<wmma::accumulator, 16, 16, 16, float> acc[2][4];
    #pragma unroll
    for (int mi = 0; mi < 2; mi++)
        #pragma unroll
        for (int ni = 0; ni < 4; ni++) wmma::fill_fragment(acc[mi][ni], 0.0f);

    auto prefetch = [&](int ks, int st) {
        const int k0 = ks * BK;
        __half* sA = base + st * STG;
        __half* sB = sA + A_SZ;
        #pragma unroll
        for (int i = 0; i < 2; i++) {
            const int c = tid + 256 * i;
            const int rA = c >> 2, cA = (c & 3) * 8;
            cp16(&sA[rA * LDA + cA], A + aBase + (size_t)rA * Kd + k0 + cA);
            const int rB = c >> 4, cB = (c & 15) * 8;
            cp16(&sB[rB * LDB + cB], B + (size_t)(k0 + rB) * N + nBase + cB);
        }
        asm volatile("cp.async.commit_group;");
    };

    prefetch(0, 0);

    for (int ks = 0; ks < nK; ks++) {
        if (ks + 1 < nK) {
            prefetch(ks + 1, (ks + 1) & 1);
            asm volatile("cp.async.wait_group 1;");
        } else {
            asm volatile("cp.async.wait_group 0;");
        }
        __syncthreads();

        const int st = ks & 1;
        const __half* sA = base + st * STG;
        const __half* sB = sA + A_SZ;

        #pragma unroll
        for (int kk = 0; kk < BK; kk += 16) {
            wmma::fragment<wmma::matrix_a, 16, 16, 16, __half, wmma::row_major> a[2];
            #pragma unroll
            for (int mi = 0; mi < 2; mi++)
                wmma::load_matrix_sync(a[mi], sA + (wm * 32 + mi * 16) * LDA + kk, LDA);
            #pragma unroll
            for (int ni = 0; ni < 4; ni++) {
                wmma::fragment<wmma::matrix_b, 16, 16, 16, __half, wmma::row_major> b;
                wmma::load_matrix_sync(b, sB + kk * LDB + wn * 64 + ni * 16, LDB);
                #pragma unroll
                for (int mi = 0; mi < 2; mi++)
                    wmma::mma_sync(acc[mi][ni], a[mi], b, acc[mi][ni]);
            }
        }
        __syncthreads();
    }

    // Epilogue in two 64-row halves (staging fits in pipeline smem union)
    #pragma unroll
    for (int half = 0; half < 2; half++) {
        if ((wm >> 1) == half) {
            #pragma unroll
            for (int mi = 0; mi < 2; mi++)
                #pragma unroll
                for (int ni = 0; ni < 4; ni++)
                    wmma::store_matrix_sync(
                        stagef + ((wm & 1) * 32 + mi * 16) * LDS_ + wn * 64 + ni * 16,
                        acc[mi][ni], LDS_, wmma::mem_row_major);
        }
        __syncthreads();
        #pragma unroll 4
        for (int i = 0; i < (64 * BN) / 256; i++) {
            const int flat = i * 256 + tid;
            const int r = flat >> 7;
            const int c = flat & 127;
            const int n = nBase + c;
            const float v = stagef[r * LDS_ + c] + __ldg(&bias[n]);
            const int m = blockIdx.y * BM + half * 64 + r;
            if (MODE == 0) {
                C[(size_t)m * N + n] = v;
            } else {
                const int b = m >> 11;
                const int s = m & 2047;
                const int c3 = n >> 9;
                const int h = (n >> 6) & 7;
                const int d = n & 63;
                float* dst = (c3 == 0) ? g_q : (c3 == 1) ? g_k : g_v;
                dst[(((size_t)b * HH + h) * SS + s) * HDIM + d] = v;
            }
        }
        __syncthreads();
    }
}

// ---------------------------------------------------------------------------
// Routed attention (round-4 v4, best measured): 2 queries per loop iteration;
// 8-lane groups own one route per query per iter; 3-level xor reduce + select.
// Output written as single fp16 in [b*S+s, h*64+d] layout (proj-GEMM A).
// ---------------------------------------------------------------------------
__global__ __launch_bounds__(256) void attn_k(const int* __restrict__ routes)
{
    const unsigned FULL = 0xffffffffu;
    const int lane = threadIdx.x & 31;
    const int warp = threadIdx.x >> 5;
    const int chunks = SS / 32;
    const int bh = blockIdx.x / chunks;
    const int sc = blockIdx.x % chunks;
    const int b = bh >> 3, h = bh & 7;
    const int sub = lane & 7;
    const int grp = lane >> 3;

    const float* Qb = g_q + (size_t)bh * SS * HDIM;
    const float* Kb = g_k + (size_t)bh * SS * HDIM;
    const float* Vb = g_v + (size_t)bh * SS * HDIM;

    #pragma unroll 1
    for (int qp = 0; qp < 2; qp++) {
        const int s0 = sc * 32 + warp * 4 + qp * 2;
        const int s1 = s0 + 1;

        const float4* qp0 = (const float4*)(Qb + (size_t)s0 * HDIM + sub * 8);
        const float4 q0a = qp0[0], q0b = qp0[1];
        const float4* qp1 = (const float4*)(Qb + (size_t)s1 * HDIM + sub * 8);
        const float4 q1a = qp1[0], q1b = qp1[1];

        const int r_lo0 = routes[s0 * KROUTE + lane];
        const int r_hi0 = routes[s0 * KROUTE + 32 + lane];
        const int r_lo1 = routes[s1 * KROUTE + lane];
        const int r_hi1 = routes[s1 * KROUTE + 32 + lane];

        float slo0 = 0.f, shi0 = 0.f, slo1 = 0.f, shi1 = 0.f;
        #pragma unroll
        for (int t = 0; t < 16; t++) {
            const int kk31 = (t * 4 + grp) & 31;
            const int r0 = __shfl_sync(FULL, (t < 8) ? r_lo0 : r_hi0, kk31);
            const int r1 = __shfl_sync(FULL, (t < 8) ? r_lo1 : r_hi1, kk31);
            const float4* kp0 = (const float4*)(Kb + (size_t)r0 * HDIM + sub * 8);
            const float4* kp1 = (const float4*)(Kb + (size_t)r1 * HDIM + sub * 8);
            const float4 k0a = kp0[0], k0b = kp0[1];
            const float4 k1a = kp1[0], k1b = kp1[1];

            float p0 = k0a.x * q0a.x;
            p0 = fmaf(k0a.y, q0a.y, p0);
            p0 = fmaf(k0a.z, q0a.z, p0);
            p0 = fmaf(k0a.w, q0a.w, p0);
            p0 = fmaf(k0b.x, q0b.x, p0);
            p0 = fmaf(k0b.y, q0b.y, p0);
            p0 = fmaf(k0b.z, q0b.z, p0);
            p0 = fmaf(k0b.w, q0b.w, p0);
            float p1 = k1a.x * q1a.x;
            p1 = fmaf(k1a.y, q1a.y, p1);
            p1 = fmaf(k1a.z, q1a.z, p1);
            p1 = fmaf(k1a.w, q1a.w, p1);
            p1 = fmaf(k1b.x, q1b.x, p1);
            p1 = fmaf(k1b.y, q1b.y, p1);
            p1 = fmaf(k1b.z, q1b.z, p1);
            p1 = fmaf(k1b.w, q1b.w, p1);

            p0 += __shfl_xor_sync(FULL, p0, 1);
            p1 += __shfl_xor_sync(FULL, p1, 1);
            p0 += __shfl_xor_sync(FULL, p0, 2);
            p1 += __shfl_xor_sync(FULL, p1, 2);
            p0 += __shfl_xor_sync(FULL, p0, 4);
            p1 += __shfl_xor_sync(FULL, p1, 4);
            const float v0 = __shfl_sync(FULL, p0, (lane & 3) * 8);
            const float v1 = __shfl_sync(FULL, p1, (lane & 3) * 8);
            if ((lane >> 2) == t)     { slo0 = v0; slo1 = v1; }
            if ((lane >> 2) + 8 == t) { shi0 = v0; shi1 = v1; }
        }
        slo0 *= 0.125f; shi0 *= 0.125f;
        slo1 *= 0.125f; shi1 *= 0.125f;

        float mx0 = fmaxf(slo0, shi0);
        float mx1 = fmaxf(slo1, shi1);
        #pragma unroll
        for (int o = 16; o; o >>= 1) {
            mx0 = fmaxf(mx0, __shfl_xor_sync(FULL, mx0, o));
            mx1 = fmaxf(mx1, __shfl_xor_sync(FULL, mx1, o));
        }
        const float elo0 = __expf(slo0 - mx0), ehi0 = __expf(shi0 - mx0);
        const float elo1 = __expf(slo1 - mx1), ehi1 = __expf(shi1 - mx1);
        float sum0 = elo0 + ehi0;
        float sum1 = elo1 + ehi1;
        #pragma unroll
        for (int o = 16; o; o >>= 1) {
            sum0 += __shfl_xor_sync(FULL, sum0, o);
            sum1 += __shfl_xor_sync(FULL, sum1, o);
        }
        const float inv0 = __fdividef(1.f, sum0);
        const float inv1 = __fdividef(1.f, sum1);
        const float wlo0 = elo0 * inv0, whi0 = ehi0 * inv0;
        const float wlo1 = elo1 * inv1, whi1 = ehi1 * inv1;

        float4 a0a = make_float4(0.f, 0.f, 0.f, 0.f);
        float4 a0b = make_float4(0.f, 0.f, 0.f, 0.f);
        float4 a1a = make_float4(0.f, 0.f, 0.f, 0.f);
        float4 a1b = make_float4(0.f, 0.f, 0.f, 0.f);
        #pragma unroll
        for (int t = 0; t < 16; t++) {
            const int kk31 = (t * 4 + grp) & 31;
            const int r0 = __shfl_sync(FULL, (t < 8) ? r_lo0 : r_hi0, kk31);
            const float w0 = __shfl_sync(FULL, (t < 8) ? wlo0 : whi0, kk31);
            const int r1 = __shfl_sync(FULL, (t < 8) ? r_lo1 : r_hi1, kk31);
            const float w1 = __shfl_sync(FULL, (t < 8) ? wlo1 : whi1, kk31);
            const float4* vp0 = (const float4*)(Vb + (size_t)r0 * HDIM + sub * 8);
            const float4* vp1 = (const float4*)(Vb + (size_t)r1 * HDIM + sub * 8);
            const float4 v0a = vp0[0], v0b = vp0[1];
            const float4 v1a = vp1[0], v1b = vp1[1];
            a0a.x = fmaf(w0, v0a.x, a0a.x);
            a0a.y = fmaf(w0, v0a.y, a0a.y);
            a0a.z = fmaf(w0, v0a.z, a0a.z);
            a0a.w = fmaf(w0, v0a.w, a0a.w);
            a0b.x = fmaf(w0, v0b.x, a0b.x);
            a0b.y = fmaf(w0, v0b.y, a0b.y);
            a0b.z = fmaf(w0, v0b.z, a0b.z);
            a0b.w = fmaf(w0, v0b.w, a0b.w);
            a1a.x = fmaf(w1, v1a.x, a1a.x);
            a1a.y = fmaf(w1, v1a.y, a1a.y);
            a1a.z = fmaf(w1, v1a.z, a1a.z);
            a1a.w = fmaf(w1, v1a.w, a1a.w);
            a1b.x = fmaf(w1, v1b.x, a1b.x);
            a1b.y = fmaf(w1, v1b.y, a1b.y);
            a1b.z = fmaf(w1, v1b.z, a1b.z);
            a1b.w = fmaf(w1, v1b.w, a1b.w);
        }
        #pragma unroll
        for (int o = 8; o <= 16; o <<= 1) {
            a0a.x += __shfl_xor_sync(FULL, a0a.x, o);
            a0a.y += __shfl_xor_sync(FULL, a0a.y, o);
            a0a.z += __shfl_xor_sync(FULL, a0a.z, o);
            a0a.w += __shfl_xor_sync(FULL, a0a.w, o);
            a0b.x += __shfl_xor_sync(FULL, a0b.x, o);
            a0b.y += __shfl_xor_sync(FULL, a0b.y, o);
            a0b.z += __shfl_xor_sync(FULL, a0b.z, o);
            a0b.w += __shfl_xor_sync(FULL, a0b.w, o);
            a1a.x += __shfl_xor_sync(FULL, a1a.x, o);
            a1a.y += __shfl_xor_sync(FULL, a1a.y, o);
            a1a.z += __shfl_xor_sync(FULL, a1a.z, o);
            a1a.w += __shfl_xor_sync(FULL, a1a.w, o);
            a1b.x += __shfl_xor_sync(FULL, a1b.x, o);
            a1b.y += __shfl_xor_sync(FULL, a1b.y, o);
            a1b.z += __shfl_xor_sync(FULL, a1b.z, o);
            a1b.w += __shfl_xor_sync(FULL, a1b.w, o);
        }

        if (lane < 8) {
            #pragma unroll
            for (int qq = 0; qq < 2; qq++) {
                const int s = s0 + qq;
                const float4 xa = qq ? a1a : a0a;
                const float4 xb = qq ? a1b : a0b;
                const size_t off = ((size_t)(b * SS + s)) * DD + h * HDIM + sub * 8;
                __half2 hp[4];
                hp[0] = __floats2half2_rn(xa.x, xa.y);
                hp[1] = __floats2half2_rn(xa.z, xa.w);
                hp[2] = __floats2half2_rn(xb.x, xb.y);
                hp[3] = __floats2half2_rn(xb.z, xb.w);
                *(uint4*)&gat[off] = *(uint4*)hp;
            }
        }
    }
}

// ---------------------------------------------------------------------------
extern "C" void kernel_launch(void* const* d_in, const int* in_sizes, int n_in,
                              void* d_out, int out_size)
{
    const float* x      = (const float*)d_in[0];
    const float* Wqkv   = (const float*)d_in[1];
    const float* bqkv   = (const float*)d_in[2];
    const float* Wout   = (const float*)d_in[3];
    const float* bout   = (const float*)d_in[4];
    const int*   routes = (const int*)d_in[5];
    float* out = (float*)d_out;

    __half *xh, *w1h, *w2h, *ath;
    cudaGetSymbolAddress((void**)&xh,  gx);
    cudaGetSymbolAddress((void**)&w1h, gw1);
    cudaGetSymbolAddress((void**)&w2h, gw2);
    cudaGetSymbolAddress((void**)&ath, gat);

    // smem: 2 stages x (128*40 + 32*136) halves = 37,888 bytes
    constexpr int SMEM_BYTES = 2 * (128 * 40 + 32 * 136) * 2;
    cudaFuncSetAttribute(gemm_fp16<0>, cudaFuncAttributeMaxDynamicSharedMemorySize, SMEM_BYTES);
    cudaFuncSetAttribute(gemm_fp16<1>, cudaFuncAttributeMaxDynamicSharedMemorySize, SMEM_BYTES);

    // 1) fp32 -> fp16 conversions
    {
        int n4 = (BB * SS * DD) / 4;
        cvt_k<<<(n4 + 255) / 256, 256>>>((const float4*)x, (__half2*)xh, n4);
        n4 = (DD * 3 * DD) / 4;
        cvt_k<<<(n4 + 255) / 256, 256>>>((const float4*)Wqkv, (__half2*)w1h, n4);
        n4 = (DD * DD) / 4;
        cvt_k<<<(n4 + 255) / 256, 256>>>((const float4*)Wout, (__half2*)w2h, n4);
    }

    // 2) QKV GEMM + head-scatter epilogue
    gemm_fp16<1><<<dim3(3 * DD / 128, (BB * SS) / 128), 256, SMEM_BYTES>>>(
        xh, w1h, bqkv, nullptr, BB * SS, 3 * DD, DD);

    // 3) routed attention (writes fp16 proj-A matrix)
    attn_k<<<BB * HH * (SS / 32), 256>>>(routes);

    // 4) out projection
    gemm_fp16<0><<<dim3(DD / 128, (BB * SS) / 128), 256, SMEM_BYTES>>>(
        ath, w2h, bout, out, BB * SS, DD, DD);
}

// round 9
// speedup vs baseline: 1.9699x; 1.2600x over previous
#include <cuda_runtime.h>
#include <cuda_fp16.h>
#include <mma.h>
#include <cstdint>
#include <cstddef>

using namespace nvcuda;

#define BB 2
#define SS 2048
#define DD 512
#define HH 8
#define HDIM 64
#define KROUTE 64

// ---------------------------------------------------------------------------
// Scratch (device globals; no allocation allowed)
// ---------------------------------------------------------------------------
__device__ float g_q[BB * HH * SS * HDIM];
__device__ __align__(16) __half gk[BB * HH * SS * HDIM];
__device__ __align__(16) __half gv[BB * HH * SS * HDIM];

__device__ __align__(16) __half gx[BB * SS * DD];
__device__ __align__(16) __half gw1[DD * 3 * DD];
__device__ __align__(16) __half gw2[DD * DD];
__device__ __align__(16) __half gat[BB * SS * DD];

// ---------------------------------------------------------------------------
__device__ __forceinline__ void cp16(void* d, const void* s)
{
    unsigned ds = (unsigned)__cvta_generic_to_shared(d);
    asm volatile("cp.async.cg.shared.global [%0], [%1], 16;" :: "r"(ds), "l"(s));
}

// ---------------------------------------------------------------------------
// fp32 -> fp16 conversion (vectorized)
// ---------------------------------------------------------------------------
__global__ __launch_bounds__(256) void cvt_k(
    const float4* __restrict__ src, __half2* __restrict__ dst, int n4)
{
    int i = blockIdx.x * 256 + threadIdx.x;
    if (i >= n4) return;
    float4 v = src[i];
    dst[2 * i + 0] = __floats2half2_rn(v.x, v.y);
    dst[2 * i + 1] = __floats2half2_rn(v.z, v.w);
}

// ---------------------------------------------------------------------------
// Tensor-core GEMM, single fp16 term, fp32 accumulate. 128x128x32 tile,
// 2-stage cp.async double buffering, 2 CTAs/SM. 8 warps: 4(m) x 2(n).
//   MODE 0: dense fp32 store   MODE 1: scatter q->fp32, k/v->fp16
// ---------------------------------------------------------------------------
template <int MODE>
__global__ __launch_bounds__(256, 2) void gemm_fp16(
    const __half* __restrict__ A, const __half* __restrict__ B,
    const float* __restrict__ bias, float* __restrict__ C,
    int M, int N, int Kd)
{
    extern __shared__ __align__(16) char smem[];
    constexpr int BM = 128, BN = 128, BK = 32;
    constexpr int LDA = BK + 8;
    constexpr int LDB = BN + 8;
    constexpr int LDS_ = BN + 4;
    constexpr int A_SZ = BM * LDA;
    constexpr int B_SZ = BK * LDB;
    constexpr int STG = A_SZ + B_SZ;

    __half* base = (__half*)smem;
    float* stagef = (float*)smem;  // union, reused after k-loop

    const int tid = threadIdx.x;
    const int wid = tid >> 5;
    const int wm = wid & 3;
    const int wn = wid >> 2;

    const size_t aBase = (size_t)blockIdx.y * BM * Kd;
    const int nBase = blockIdx.x * BN;
    const int nK = Kd / BK;

    wmma::fragment<wmma::accumulator, 16, 16, 16, float> acc[2][4];
    #pragma unroll
    for (int mi = 0; mi < 2; mi++)
        #pragma unroll
        for (int ni = 0; ni < 4; ni++) wmma::fill_fragment(acc[mi][ni], 0.0f);

    auto prefetch = [&](int ks, int st) {
        const int k0 = ks * BK;
        __half* sA = base + st * STG;
        __half* sB = sA + A_SZ;
        #pragma unroll
        for (int i = 0; i < 2; i++) {
            const int c = tid + 256 * i;
            const int rA = c >> 2, cA = (c & 3) * 8;
            cp16(&sA[rA * LDA + cA], A + aBase + (size_t)rA * Kd + k0 + cA);
            const int rB = c >> 4, cB = (c & 15) * 8;
            cp16(&sB[rB * LDB + cB], B + (size_t)(k0 + rB) * N + nBase + cB);
        }
        asm volatile("cp.async.commit_group;");
    };

    prefetch(0, 0);

    for (int ks = 0; ks < nK; ks++) {
        if (ks + 1 < nK) {
            prefetch(ks + 1, (ks + 1) & 1);
            asm volatile("cp.async.wait_group 1;");
        } else {
            asm volatile("cp.async.wait_group 0;");
        }
        __syncthreads();

        const int st = ks & 1;
        const __half* sA = base + st * STG;
        const __half* sB = sA + A_SZ;

        #pragma unroll
        for (int kk = 0; kk < BK; kk += 16) {
            wmma::fragment<wmma::matrix_a, 16, 16, 16, __half, wmma::row_major> a[2];
            #pragma unroll
            for (int mi = 0; mi < 2; mi++)
                wmma::load_matrix_sync(a[mi], sA + (wm * 32 + mi * 16) * LDA + kk, LDA);
            #pragma unroll
            for (int ni = 0; ni < 4; ni++) {
                wmma::fragment<wmma::matrix_b, 16, 16, 16, __half, wmma::row_major> b;
                wmma::load_matrix_sync(b, sB + kk * LDB + wn * 64 + ni * 16, LDB);
                #pragma unroll
                for (int mi = 0; mi < 2; mi++)
                    wmma::mma_sync(acc[mi][ni], a[mi], b, acc[mi][ni]);
            }
        }
        __syncthreads();
    }

    // Epilogue in two 64-row halves
    #pragma unroll
    for (int half = 0; half < 2; half++) {
        if ((wm >> 1) == half) {
            #pragma unroll
            for (int mi = 0; mi < 2; mi++)
                #pragma unroll
                for (int ni = 0; ni < 4; ni++)
                    wmma::store_matrix_sync(
                        stagef + ((wm & 1) * 32 + mi * 16) * LDS_ + wn * 64 + ni * 16,
                        acc[mi][ni], LDS_, wmma::mem_row_major);
        }
        __syncthreads();
        #pragma unroll 4
        for (int i = 0; i < (64 * BN) / 256; i++) {
            const int flat = i * 256 + tid;
            const int r = flat >> 7;
            const int c = flat & 127;
            const int n = nBase + c;
            const float v = stagef[r * LDS_ + c] + __ldg(&bias[n]);
            const int m = blockIdx.y * BM + half * 64 + r;
            if (MODE == 0) {
                C[(size_t)m * N + n] = v;
            } else {
                const int b = m >> 11;
                const int s = m & 2047;
                const int c3 = n >> 9;
                const int h = (n >> 6) & 7;
                const int d = n & 63;
                const size_t off = (((size_t)b * HH + h) * SS + s) * HDIM + d;
                if (c3 == 0)      g_q[off] = v;
                else if (c3 == 1) gk[off] = __float2half_rn(v);
                else              gv[off] = __float2half_rn(v);
            }
        }
        __syncthreads();
    }
}

// ---------------------------------------------------------------------------
// Routed attention: 2 queries per loop iteration; 8-lane groups own one route
// per query per iter. K/V gathered as fp16 (one LDG.128 per route-slice),
// converted to fp32 for math. Output fp16 in proj-GEMM A layout.
// ---------------------------------------------------------------------------
__global__ __launch_bounds__(256) void attn_k(const int* __restrict__ routes)
{
    const unsigned FULL = 0xffffffffu;
    const int lane = threadIdx.x & 31;
    const int warp = threadIdx.x >> 5;
    const int chunks = SS / 32;
    const int bh = blockIdx.x / chunks;
    const int sc = blockIdx.x % chunks;
    const int b = bh >> 3, h = bh & 7;
    const int sub = lane & 7;
    const int grp = lane >> 3;

    const float*  Qb = g_q + (size_t)bh * SS * HDIM;
    const __half* Kb = gk + (size_t)bh * SS * HDIM;
    const __half* Vb = gv + (size_t)bh * SS * HDIM;

    #pragma unroll 1
    for (int qp = 0; qp < 2; qp++) {
        const int s0 = sc * 32 + warp * 4 + qp * 2;
        const int s1 = s0 + 1;

        const float4* qp0 = (const float4*)(Qb + (size_t)s0 * HDIM + sub * 8);
        const float4 q0a = qp0[0], q0b = qp0[1];
        const float4* qp1 = (const float4*)(Qb + (size_t)s1 * HDIM + sub * 8);
        const float4 q1a = qp1[0], q1b = qp1[1];

        const int r_lo0 = routes[s0 * KROUTE + lane];
        const int r_hi0 = routes[s0 * KROUTE + 32 + lane];
        const int r_lo1 = routes[s1 * KROUTE + lane];
        const int r_hi1 = routes[s1 * KROUTE + 32 + lane];

        float slo0 = 0.f, shi0 = 0.f, slo1 = 0.f, shi1 = 0.f;
        #pragma unroll
        for (int t = 0; t < 16; t++) {
            const int kk31 = (t * 4 + grp) & 31;
            const int r0 = __shfl_sync(FULL, (t < 8) ? r_lo0 : r_hi0, kk31);
            const int r1 = __shfl_sync(FULL, (t < 8) ? r_lo1 : r_hi1, kk31);
            const uint4 kr0 = *(const uint4*)(Kb + (size_t)r0 * HDIM + sub * 8);
            const uint4 kr1 = *(const uint4*)(Kb + (size_t)r1 * HDIM + sub * 8);
            const __half2* kh0 = (const __half2*)&kr0;
            const __half2* kh1 = (const __half2*)&kr1;
            const float2 ka0 = __half22float2(kh0[0]);
            const float2 kb0 = __half22float2(kh0[1]);
            const float2 kc0 = __half22float2(kh0[2]);
            const float2 kd0 = __half22float2(kh0[3]);
            const float2 ka1 = __half22float2(kh1[0]);
            const float2 kb1 = __half22float2(kh1[1]);
            const float2 kc1 = __half22float2(kh1[2]);
            const float2 kd1 = __half22float2(kh1[3]);

            float p0 = ka0.x * q0a.x;
            p0 = fmaf(ka0.y, q0a.y, p0);
            p0 = fmaf(kb0.x, q0a.z, p0);
            p0 = fmaf(kb0.y, q0a.w, p0);
            p0 = fmaf(kc0.x, q0b.x, p0);
            p0 = fmaf(kc0.y, q0b.y, p0);
            p0 = fmaf(kd0.x, q0b.z, p0);
            p0 = fmaf(kd0.y, q0b.w, p0);
            float p1 = ka1.x * q1a.x;
            p1 = fmaf(ka1.y, q1a.y, p1);
            p1 = fmaf(kb1.x, q1a.z, p1);
            p1 = fmaf(kb1.y, q1a.w, p1);
            p1 = fmaf(kc1.x, q1b.x, p1);
            p1 = fmaf(kc1.y, q1b.y, p1);
            p1 = fmaf(kd1.x, q1b.z, p1);
            p1 = fmaf(kd1.y, q1b.w, p1);

            p0 += __shfl_xor_sync(FULL, p0, 1);
            p1 += __shfl_xor_sync(FULL, p1, 1);
            p0 += __shfl_xor_sync(FULL, p0, 2);
            p1 += __shfl_xor_sync(FULL, p1, 2);
            p0 += __shfl_xor_sync(FULL, p0, 4);
            p1 += __shfl_xor_sync(FULL, p1, 4);
            const float v0 = __shfl_sync(FULL, p0, (lane & 3) * 8);
            const float v1 = __shfl_sync(FULL, p1, (lane & 3) * 8);
            if ((lane >> 2) == t)     { slo0 = v0; slo1 = v1; }
            if ((lane >> 2) + 8 == t) { shi0 = v0; shi1 = v1; }
        }
        slo0 *= 0.125f; shi0 *= 0.125f;
        slo1 *= 0.125f; shi1 *= 0.125f;

        float mx0 = fmaxf(slo0, shi0);
        float mx1 = fmaxf(slo1, shi1);
        #pragma unroll
        for (int o = 16; o; o >>= 1) {
            mx0 = fmaxf(mx0, __shfl_xor_sync(FULL, mx0, o));
            mx1 = fmaxf(mx1, __shfl_xor_sync(FULL, mx1, o));
        }
        const float elo0 = __expf(slo0 - mx0), ehi0 = __expf(shi0 - mx0);
        const float elo1 = __expf(slo1 - mx1), ehi1 = __expf(shi1 - mx1);
        float sum0 = elo0 + ehi0;
        float sum1 = elo1 + ehi1;
        #pragma unroll
        for (int o = 16; o; o >>= 1) {
            sum0 += __shfl_xor_sync(FULL, sum0, o);
            sum1 += __shfl_xor_sync(FULL, sum1, o);
        }
        const float inv0 = __fdividef(1.f, sum0);
        const float inv1 = __fdividef(1.f, sum1);
        const float wlo0 = elo0 * inv0, whi0 = ehi0 * inv0;
        const float wlo1 = elo1 * inv1, whi1 = ehi1 * inv1;

        float4 a0a = make_float4(0.f, 0.f, 0.f, 0.f);
        float4 a0b = make_float4(0.f, 0.f, 0.f, 0.f);
        float4 a1a = make_float4(0.f, 0.f, 0.f, 0.f);
        float4 a1b = make_float4(0.f, 0.f, 0.f, 0.f);
        #pragma unroll
        for (int t = 0; t < 16; t++) {
            const int kk31 = (t * 4 + grp) & 31;
            const int r0 = __shfl_sync(FULL, (t < 8) ? r_lo0 : r_hi0, kk31);
            const float w0 = __shfl_sync(FULL, (t < 8) ? wlo0 : whi0, kk31);
            const int r1 = __shfl_sync(FULL, (t < 8) ? r_lo1 : r_hi1, kk31);
            const float w1 = __shfl_sync(FULL, (t < 8) ? wlo1 : whi1, kk31);
            const uint4 vr0 = *(const uint4*)(Vb + (size_t)r0 * HDIM + sub * 8);
            const uint4 vr1 = *(const uint4*)(Vb + (size_t)r1 * HDIM + sub * 8);
            const __half2* vh0 = (const __half2*)&vr0;
            const __half2* vh1 = (const __half2*)&vr1;
            const float2 va0 = __half22float2(vh0[0]);
            const float2 vb0 = __half22float2(vh0[1]);
            const float2 vc0 = __half22float2(vh0[2]);
            const float2 vd0 = __half22float2(vh0[3]);
            const float2 va1 = __half22float2(vh1[0]);
            const float2 vb1 = __half22float2(vh1[1]);
            const float2 vc1 = __half22float2(vh1[2]);
            const float2 vd1 = __half22float2(vh1[3]);
            a0a.x = fmaf(w0, va0.x, a0a.x);
            a0a.y = fmaf(w0, va0.y, a0a.y);
            a0a.z = fmaf(w0, vb0.x, a0a.z);
            a0a.w = fmaf(w0, vb0.y, a0a.w);
            a0b.x = fmaf(w0, vc0.x, a0b.x);
            a0b.y = fmaf(w0, vc0.y, a0b.y);
            a0b.z = fmaf(w0, vd0.x, a0b.z);
            a0b.w = fmaf(w0, vd0.y, a0b.w);
            a1a.x = fmaf(w1, va1.x, a1a.x);
            a1a.y = fmaf(w1, va1.y, a1a.y);
            a1a.z = fmaf(w1, vb1.x, a1a.z);
            a1a.w = fmaf(w1, vb1.y, a1a.w);
            a1b.x = fmaf(w1, vc1.x, a1b.x);
            a1b.y = fmaf(w1, vc1.y, a1b.y);
            a1b.z = fmaf(w1, vd1.x, a1b.z);
            a1b.w = fmaf(w1, vd1.y, a1b.w);
        }
        #pragma unroll
        for (int o = 8; o <= 16; o <<= 1) {
            a0a.x += __shfl_xor_sync(FULL, a0a.x, o);
            a0a.y += __shfl_xor_sync(FULL, a0a.y, o);
            a0a.z += __shfl_xor_sync(FULL, a0a.z, o);
            a0a.w += __shfl_xor_sync(FULL, a0a.w, o);
            a0b.x += __shfl_xor_sync(FULL, a0b.x, o);
            a0b.y += __shfl_xor_sync(FULL, a0b.y, o);
            a0b.z += __shfl_xor_sync(FULL, a0b.z, o);
            a0b.w += __shfl_xor_sync(FULL, a0b.w, o);
            a1a.x += __shfl_xor_sync(FULL, a1a.x, o);
            a1a.y += __shfl_xor_sync(FULL, a1a.y, o);
            a1a.z += __shfl_xor_sync(FULL, a1a.z, o);
            a1a.w += __shfl_xor_sync(FULL, a1a.w, o);
            a1b.x += __shfl_xor_sync(FULL, a1b.x, o);
            a1b.y += __shfl_xor_sync(FULL, a1b.y, o);
            a1b.z += __shfl_xor_sync(FULL, a1b.z, o);
            a1b.w += __shfl_xor_sync(FULL, a1b.w, o);
        }

        if (lane < 8) {
            #pragma unroll
            for (int qq = 0; qq < 2; qq++) {
                const int s = s0 + qq;
                const float4 xa = qq ? a1a : a0a;
                const float4 xb = qq ? a1b : a0b;
                const size_t off = ((size_t)(b * SS + s)) * DD + h * HDIM + sub * 8;
                __half2 hp[4];
                hp[0] = __floats2half2_rn(xa.x, xa.y);
                hp[1] = __floats2half2_rn(xa.z, xa.w);
                hp[2] = __floats2half2_rn(xb.x, xb.y);
                hp[3] = __floats2half2_rn(xb.z, xb.w);
                *(uint4*)&gat[off] = *(uint4*)hp;
            }
        }
    }
}

// ---------------------------------------------------------------------------
extern "C" void kernel_launch(void* const* d_in, const int* in_sizes, int n_in,
                              void* d_out, int out_size)
{
    const float* x      = (const float*)d_in[0];
    const float* Wqkv   = (const float*)d_in[1];
    const float* bqkv   = (const float*)d_in[2];
    const float* Wout   = (const float*)d_in[3];
    const float* bout   = (const float*)d_in[4];
    const int*   routes = (const int*)d_in[5];
    float* out = (float*)d_out;

    __half *xh, *w1h, *w2h, *ath;
    cudaGetSymbolAddress((void**)&xh,  gx);
    cudaGetSymbolAddress((void**)&w1h, gw1);
    cudaGetSymbolAddress((void**)&w2h, gw2);
    cudaGetSymbolAddress((void**)&ath, gat);

    constexpr int SMEM_BYTES = 2 * (128 * 40 + 32 * 136) * 2;
    cudaFuncSetAttribute(gemm_fp16<0>, cudaFuncAttributeMaxDynamicSharedMemorySize, SMEM_BYTES);
    cudaFuncSetAttribute(gemm_fp16<1>, cudaFuncAttributeMaxDynamicSharedMemorySize, SMEM_BYTES);

    // 1) fp32 -> fp16 conversions
    {
        int n4 = (BB * SS * DD) / 4;
        cvt_k<<<(n4 + 255) / 256, 256>>>((const float4*)x, (__half2*)xh, n4);
        n4 = (DD * 3 * DD) / 4;
        cvt_k<<<(n4 + 255) / 256, 256>>>((const float4*)Wqkv, (__half2*)w1h, n4);
        n4 = (DD * DD) / 4;
        cvt_k<<<(n4 + 255) / 256, 256>>>((const float4*)Wout, (__half2*)w2h, n4);
    }

    // 2) QKV GEMM + head-scatter epilogue (q fp32, k/v fp16)
    gemm_fp16<1><<<dim3(3 * DD / 128, (BB * SS) / 128), 256, SMEM_BYTES>>>(
        xh, w1h, bqkv, nullptr, BB * SS, 3 * DD, DD);

    // 3) routed attention (fp16 K/V gather, writes fp16 proj-A matrix)
    attn_k<<<BB * HH * (SS / 32), 256>>>(routes);

    // 4) out projection
    gemm_fp16<0><<<dim3(DD / 128, (BB * SS) / 128), 256, SMEM_BYTES>>>(
        ath, w2h, bout, out, BB * SS, DD, DD);
}

// round 10
// speedup vs baseline: 2.2398x; 1.1371x over previous
#include <cuda_runtime.h>
#include <cuda_fp16.h>
#include <mma.h>
#include <cstdint>
#include <cstddef>

using namespace nvcuda;

#define BB 2
#define SS 2048
#define DD 512
#define HH 8
#define HDIM 64
#define KROUTE 64

// ---------------------------------------------------------------------------
// Scratch (device globals; no allocation allowed)
// ---------------------------------------------------------------------------
__device__ float g_q[BB * HH * SS * HDIM];
__device__ __align__(16) __half gk[BB * HH * SS * HDIM];
__device__ __align__(16) __half gv[BB * HH * SS * HDIM];

__device__ __align__(16) __half gx[BB * SS * DD];
__device__ __align__(16) __half gw1[DD * 3 * DD];
__device__ __align__(16) __half gw2[DD * DD];
__device__ __align__(16) __half gat[BB * SS * DD];

// ---------------------------------------------------------------------------
__device__ __forceinline__ void cp16(void* d, const void* s)
{
    unsigned ds = (unsigned)__cvta_generic_to_shared(d);
    asm volatile("cp.async.cg.shared.global [%0], [%1], 16;" :: "r"(ds), "l"(s));
}

// ---------------------------------------------------------------------------
// Fused fp32 -> fp16 conversion for x, Wqkv, Wout (single launch)
// ---------------------------------------------------------------------------
#define N4_X  ((BB * SS * DD) / 4)
#define N4_W1 ((DD * 3 * DD) / 4)
#define N4_W2 ((DD * DD) / 4)

__global__ __launch_bounds__(256) void cvt_all(
    const float4* __restrict__ x, const float4* __restrict__ w1,
    const float4* __restrict__ w2)
{
    int i = blockIdx.x * 256 + threadIdx.x;
    const float4* src;
    __half2* dst;
    if (i < N4_X) {
        src = x + i;
        dst = (__half2*)gx + 2 * i;
    } else if (i < N4_X + N4_W1) {
        const int j = i - N4_X;
        src = w1 + j;
        dst = (__half2*)gw1 + 2 * j;
    } else if (i < N4_X + N4_W1 + N4_W2) {
        const int j = i - N4_X - N4_W1;
        src = w2 + j;
        dst = (__half2*)gw2 + 2 * j;
    } else {
        return;
    }
    const float4 v = *src;
    dst[0] = __floats2half2_rn(v.x, v.y);
    dst[1] = __floats2half2_rn(v.z, v.w);
}

// ---------------------------------------------------------------------------
// Tensor-core GEMM, single fp16 term, fp32 accumulate. 128x128x32 tile,
// 2-stage cp.async double buffering, 2 CTAs/SM. 8 warps: 4(m) x 2(n).
//   MODE 0: dense fp32 store (float2/thread)
//   MODE 1: scatter q->fp32 (float2), k/v->fp16 (half2)
// ---------------------------------------------------------------------------
template <int MODE>
__global__ __launch_bounds__(256, 2) void gemm_fp16(
    const __half* __restrict__ A, const __half* __restrict__ B,
    const float* __restrict__ bias, float* __restrict__ C,
    int M, int N, int Kd)
{
    extern __shared__ __align__(16) char smem[];
    constexpr int BM = 128, BN = 128, BK = 32;
    constexpr int LDA = BK + 8;
    constexpr int LDB = BN + 8;
    constexpr int LDS_ = BN + 4;
    constexpr int A_SZ = BM * LDA;
    constexpr int B_SZ = BK * LDB;
    constexpr int STG = A_SZ + B_SZ;

    __half* base = (__half*)smem;
    float* stagef = (float*)smem;  // union, reused after k-loop

    const int tid = threadIdx.x;
    const int wid = tid >> 5;
    const int wm = wid & 3;
    const int wn = wid >> 2;

    const size_t aBase = (size_t)blockIdx.y * BM * Kd;
    const int nBase = blockIdx.x * BN;
    const int nK = Kd / BK;

    wmma::fragment<wmma::accumulator, 16, 16, 16, float> acc[2][4];
    #pragma unroll
    for (int mi = 0; mi < 2; mi++)
        #pragma unroll
        for (int ni = 0; ni < 4; ni++) wmma::fill_fragment(acc[mi][ni], 0.0f);

    auto prefetch = [&](int ks, int st) {
        const int k0 = ks * BK;
        __half* sA = base + st * STG;
        __half* sB = sA + A_SZ;
        #pragma unroll
        for (int i = 0; i < 2; i++) {
            const int c = tid + 256 * i;
            const int rA = c >> 2, cA = (c & 3) * 8;
            cp16(&sA[rA * LDA + cA], A + aBase + (size_t)rA * Kd + k0 + cA);
            const int rB = c >> 4, cB = (c & 15) * 8;
            cp16(&sB[rB * LDB + cB], B + (size_t)(k0 + rB) * N + nBase + cB);
        }
        asm volatile("cp.async.commit_group;");
    };

    prefetch(0, 0);

    for (int ks = 0; ks < nK; ks++) {
        if (ks + 1 < nK) {
            prefetch(ks + 1, (ks + 1) & 1);
            asm volatile("cp.async.wait_group 1;");
        } else {
            asm volatile("cp.async.wait_group 0;");
        }
        __syncthreads();

        const int st = ks & 1;
        const __half* sA = base + st * STG;
        const __half* sB = sA + A_SZ;

        #pragma unroll
        for (int kk = 0; kk < BK; kk += 16) {
            wmma::fragment<wmma::matrix_a, 16, 16, 16, __half, wmma::row_major> a[2];
            #pragma unroll
            for (int mi = 0; mi < 2; mi++)
                wmma::load_matrix_sync(a[mi], sA + (wm * 32 + mi * 16) * LDA + kk, LDA);
            #pragma unroll
            for (int ni = 0; ni < 4; ni++) {
                wmma::fragment<wmma::matrix_b, 16, 16, 16, __half, wmma::row_major> b;
                wmma::load_matrix_sync(b, sB + kk * LDB + wn * 64 + ni * 16, LDB);
                #pragma unroll
                for (int mi = 0; mi < 2; mi++)
                    wmma::mma_sync(acc[mi][ni], a[mi], b, acc[mi][ni]);
            }
        }
        __syncthreads();
    }

    // Epilogue in two 64-row halves; each thread handles 2 consecutive cols.
    #pragma unroll
    for (int half = 0; half < 2; half++) {
        if ((wm >> 1) == half) {
            #pragma unroll
            for (int mi = 0; mi < 2; mi++)
                #pragma unroll
                for (int ni = 0; ni < 4; ni++)
                    wmma::store_matrix_sync(
                        stagef + ((wm & 1) * 32 + mi * 16) * LDS_ + wn * 64 + ni * 16,
                        acc[mi][ni], LDS_, wmma::mem_row_major);
        }
        __syncthreads();
        #pragma unroll 4
        for (int i = 0; i < (64 * BN) / (256 * 2); i++) {
            const int flat = i * 256 + tid;       // half2 index
            const int r = flat >> 6;              // 0..63
            const int c2 = flat & 63;             // column pair
            const int n = nBase + c2 * 2;
            const float v0 = stagef[r * LDS_ + c2 * 2 + 0] + __ldg(&bias[n + 0]);
            const float v1 = stagef[r * LDS_ + c2 * 2 + 1] + __ldg(&bias[n + 1]);
            const int m = blockIdx.y * BM + half * 64 + r;
            if (MODE == 0) {
                *(float2*)&C[(size_t)m * N + n] = make_float2(v0, v1);
            } else {
                const int b = m >> 11;
                const int s = m & 2047;
                const int c3 = n >> 9;
                const int h = (n >> 6) & 7;
                const int d = n & 63;
                const size_t off = (((size_t)b * HH + h) * SS + s) * HDIM + d;
                if (c3 == 0)      *(float2*)&g_q[off] = make_float2(v0, v1);
                else if (c3 == 1) *(__half2*)&gk[off] = __floats2half2_rn(v0, v1);
                else              *(__half2*)&gv[off] = __floats2half2_rn(v0, v1);
            }
        }
        __syncthreads();
    }
}

// ---------------------------------------------------------------------------
// Routed attention: 2 queries per loop iteration; 8-lane groups own one route
// per query per iter. K/V gathered as fp16 (one LDG.128 per route-slice),
// converted to fp32 for math. Output fp16 in proj-GEMM A layout.
// ---------------------------------------------------------------------------
__global__ __launch_bounds__(256) void attn_k(const int* __restrict__ routes)
{
    const unsigned FULL = 0xffffffffu;
    const int lane = threadIdx.x & 31;
    const int warp = threadIdx.x >> 5;
    const int chunks = SS / 32;
    const int bh = blockIdx.x / chunks;
    const int sc = blockIdx.x % chunks;
    const int b = bh >> 3, h = bh & 7;
    const int sub = lane & 7;
    const int grp = lane >> 3;

    const float*  Qb = g_q + (size_t)bh * SS * HDIM;
    const __half* Kb = gk + (size_t)bh * SS * HDIM;
    const __half* Vb = gv + (size_t)bh * SS * HDIM;

    #pragma unroll 1
    for (int qp = 0; qp < 2; qp++) {
        const int s0 = sc * 32 + warp * 4 + qp * 2;
        const int s1 = s0 + 1;

        const float4* qp0 = (const float4*)(Qb + (size_t)s0 * HDIM + sub * 8);
        const float4 q0a = qp0[0], q0b = qp0[1];
        const float4* qp1 = (const float4*)(Qb + (size_t)s1 * HDIM + sub * 8);
        const float4 q1a = qp1[0], q1b = qp1[1];

        const int r_lo0 = routes[s0 * KROUTE + lane];
        const int r_hi0 = routes[s0 * KROUTE + 32 + lane];
        const int r_lo1 = routes[s1 * KROUTE + lane];
        const int r_hi1 = routes[s1 * KROUTE + 32 + lane];

        float slo0 = 0.f, shi0 = 0.f, slo1 = 0.f, shi1 = 0.f;
        #pragma unroll
        for (int t = 0; t < 16; t++) {
            const int kk31 = (t * 4 + grp) & 31;
            const int r0 = __shfl_sync(FULL, (t < 8) ? r_lo0 : r_hi0, kk31);
            const int r1 = __shfl_sync(FULL, (t < 8) ? r_lo1 : r_hi1, kk31);
            const uint4 kr0 = *(const uint4*)(Kb + (size_t)r0 * HDIM + sub * 8);
            const uint4 kr1 = *(const uint4*)(Kb + (size_t)r1 * HDIM + sub * 8);
            const __half2* kh0 = (const __half2*)&kr0;
            const __half2* kh1 = (const __half2*)&kr1;
            const float2 ka0 = __half22float2(kh0[0]);
            const float2 kb0 = __half22float2(kh0[1]);
            const float2 kc0 = __half22float2(kh0[2]);
            const float2 kd0 = __half22float2(kh0[3]);
            const float2 ka1 = __half22float2(kh1[0]);
            const float2 kb1 = __half22float2(kh1[1]);
            const float2 kc1 = __half22float2(kh1[2]);
            const float2 kd1 = __half22float2(kh1[3]);

            float p0 = ka0.x * q0a.x;
            p0 = fmaf(ka0.y, q0a.y, p0);
            p0 = fmaf(kb0.x, q0a.z, p0);
            p0 = fmaf(kb0.y, q0a.w, p0);
            p0 = fmaf(kc0.x, q0b.x, p0);
            p0 = fmaf(kc0.y, q0b.y, p0);
            p0 = fmaf(kd0.x, q0b.z, p0);
            p0 = fmaf(kd0.y, q0b.w, p0);
            float p1 = ka1.x * q1a.x;
            p1 = fmaf(ka1.y, q1a.y, p1);
            p1 = fmaf(kb1.x, q1a.z, p1);
            p1 = fmaf(kb1.y, q1a.w, p1);
            p1 = fmaf(kc1.x, q1b.x, p1);
            p1 = fmaf(kc1.y, q1b.y, p1);
            p1 = fmaf(kd1.x, q1b.z, p1);
            p1 = fmaf(kd1.y, q1b.w, p1);

            p0 += __shfl_xor_sync(FULL, p0, 1);
            p1 += __shfl_xor_sync(FULL, p1, 1);
            p0 += __shfl_xor_sync(FULL, p0, 2);
            p1 += __shfl_xor_sync(FULL, p1, 2);
            p0 += __shfl_xor_sync(FULL, p0, 4);
            p1 += __shfl_xor_sync(FULL, p1, 4);
            const float v0 = __shfl_sync(FULL, p0, (lane & 3) * 8);
            const float v1 = __shfl_sync(FULL, p1, (lane & 3) * 8);
            if ((lane >> 2) == t)     { slo0 = v0; slo1 = v1; }
            if ((lane >> 2) + 8 == t) { shi0 = v0; shi1 = v1; }
        }
        slo0 *= 0.125f; shi0 *= 0.125f;
        slo1 *= 0.125f; shi1 *= 0.125f;

        float mx0 = fmaxf(slo0, shi0);
        float mx1 = fmaxf(slo1, shi1);
        #pragma unroll
        for (int o = 16; o; o >>= 1) {
            mx0 = fmaxf(mx0, __shfl_xor_sync(FULL, mx0, o));
            mx1 = fmaxf(mx1, __shfl_xor_sync(FULL, mx1, o));
        }
        const float elo0 = __expf(slo0 - mx0), ehi0 = __expf(shi0 - mx0);
        const float elo1 = __expf(slo1 - mx1), ehi1 = __expf(shi1 - mx1);
        float sum0 = elo0 + ehi0;
        float sum1 = elo1 + ehi1;
        #pragma unroll
        for (int o = 16; o; o >>= 1) {
            sum0 += __shfl_xor_sync(FULL, sum0, o);
            sum1 += __shfl_xor_sync(FULL, sum1, o);
        }
        const float inv0 = __fdividef(1.f, sum0);
        const float inv1 = __fdividef(1.f, sum1);
        const float wlo0 = elo0 * inv0, whi0 = ehi0 * inv0;
        const float wlo1 = elo1 * inv1, whi1 = ehi1 * inv1;

        float4 a0a = make_float4(0.f, 0.f, 0.f, 0.f);
        float4 a0b = make_float4(0.f, 0.f, 0.f, 0.f);
        float4 a1a = make_float4(0.f, 0.f, 0.f, 0.f);
        float4 a1b = make_float4(0.f, 0.f, 0.f, 0.f);
        #pragma unroll
        for (int t = 0; t < 16; t++) {
            const int kk31 = (t * 4 + grp) & 31;
            const int r0 = __shfl_sync(FULL, (t < 8) ? r_lo0 : r_hi0, kk31);
            const float w0 = __shfl_sync(FULL, (t < 8) ? wlo0 : whi0, kk31);
            const int r1 = __shfl_sync(FULL, (t < 8) ? r_lo1 : r_hi1, kk31);
            const float w1 = __shfl_sync(FULL, (t < 8) ? wlo1 : whi1, kk31);
            const uint4 vr0 = *(const uint4*)(Vb + (size_t)r0 * HDIM + sub * 8);
            const uint4 vr1 = *(const uint4*)(Vb + (size_t)r1 * HDIM + sub * 8);
            const __half2* vh0 = (const __half2*)&vr0;
            const __half2* vh1 = (const __half2*)&vr1;
            const float2 va0 = __half22float2(vh0[0]);
            const float2 vb0 = __half22float2(vh0[1]);
            const float2 vc0 = __half22float2(vh0[2]);
            const float2 vd0 = __half22float2(vh0[3]);
            const float2 va1 = __half22float2(vh1[0]);
            const float2 vb1 = __half22float2(vh1[1]);
            const float2 vc1 = __half22float2(vh1[2]);
            const float2 vd1 = __half22float2(vh1[3]);
            a0a.x = fmaf(w0, va0.x, a0a.x);
            a0a.y = fmaf(w0, va0.y, a0a.y);
            a0a.z = fmaf(w0, vb0.x, a0a.z);
            a0a.w = fmaf(w0, vb0.y, a0a.w);
            a0b.x = fmaf(w0, vc0.x, a0b.x);
            a0b.y = fmaf(w0, vc0.y, a0b.y);
            a0b.z = fmaf(w0, vd0.x, a0b.z);
            a0b.w = fmaf(w0, vd0.y, a0b.w);
            a1a.x = fmaf(w1, va1.x, a1a.x);
            a1a.y = fmaf(w1, va1.y, a1a.y);
            a1a.z = fmaf(w1, vb1.x, a1a.z);
            a1a.w = fmaf(w1, vb1.y, a1a.w);
            a1b.x = fmaf(w1, vc1.x, a1b.x);
            a1b.y = fmaf(w1, vc1.y, a1b.y);
            a1b.z = fmaf(w1, vd1.x, a1b.z);
            a1b.w = fmaf(w1, vd1.y, a1b.w);
        }
        #pragma unroll
        for (int o = 8; o <= 16; o <<= 1) {
            a0a.x += __shfl_xor_sync(FULL, a0a.x, o);
            a0a.y += __shfl_xor_sync(FULL, a0a.y, o);
            a0a.z += __shfl_xor_sync(FULL, a0a.z, o);
            a0a.w += __shfl_xor_sync(FULL, a0a.w, o);
            a0b.x += __shfl_xor_sync(FULL, a0b.x, o);
            a0b.y += __shfl_xor_sync(FULL, a0b.y, o);
            a0b.z += __shfl_xor_sync(FULL, a0b.z, o);
            a0b.w += __shfl_xor_sync(FULL, a0b.w, o);
            a1a.x += __shfl_xor_sync(FULL, a1a.x, o);
            a1a.y += __shfl_xor_sync(FULL, a1a.y, o);
            a1a.z += __shfl_xor_sync(FULL, a1a.z, o);
            a1a.w += __shfl_xor_sync(FULL, a1a.w, o);
            a1b.x += __shfl_xor_sync(FULL, a1b.x, o);
            a1b.y += __shfl_xor_sync(FULL, a1b.y, o);
            a1b.z += __shfl_xor_sync(FULL, a1b.z, o);
            a1b.w += __shfl_xor_sync(FULL, a1b.w, o);
        }

        if (lane < 8) {
            #pragma unroll
            for (int qq = 0; qq < 2; qq++) {
                const int s = s0 + qq;
                const float4 xa = qq ? a1a : a0a;
                const float4 xb = qq ? a1b : a0b;
                const size_t off = ((size_t)(b * SS + s)) * DD + h * HDIM + sub * 8;
                __half2 hp[4];
                hp[0] = __floats2half2_rn(xa.x, xa.y);
                hp[1] = __floats2half2_rn(xa.z, xa.w);
                hp[2] = __floats2half2_rn(xb.x, xb.y);
                hp[3] = __floats2half2_rn(xb.z, xb.w);
                *(uint4*)&gat[off] = *(uint4*)hp;
            }
        }
    }
}

// ---------------------------------------------------------------------------
extern "C" void kernel_launch(void* const* d_in, const int* in_sizes, int n_in,
                              void* d_out, int out_size)
{
    const float* x      = (const float*)d_in[0];
    const float* Wqkv   = (const float*)d_in[1];
    const float* bqkv   = (const float*)d_in[2];
    const float* Wout   = (const float*)d_in[3];
    const float* bout   = (const float*)d_in[4];
    const int*   routes = (const int*)d_in[5];
    float* out = (float*)d_out;

    __half *ath;
    cudaGetSymbolAddress((void**)&ath, gat);
    __half *xh, *w1h, *w2h;
    cudaGetSymbolAddress((void**)&xh,  gx);
    cudaGetSymbolAddress((void**)&w1h, gw1);
    cudaGetSymbolAddress((void**)&w2h, gw2);

    constexpr int SMEM_BYTES = 2 * (128 * 40 + 32 * 136) * 2;
    cudaFuncSetAttribute(gemm_fp16<0>, cudaFuncAttributeMaxDynamicSharedMemorySize, SMEM_BYTES);
    cudaFuncSetAttribute(gemm_fp16<1>, cudaFuncAttributeMaxDynamicSharedMemorySize, SMEM_BYTES);

    // 1) fused fp32 -> fp16 conversions (one launch)
    {
        constexpr int TOT = N4_X + N4_W1 + N4_W2;
        cvt_all<<<(TOT + 255) / 256, 256>>>(
            (const float4*)x, (const float4*)Wqkv, (const float4*)Wout);
    }

    // 2) QKV GEMM + head-scatter epilogue (q fp32, k/v fp16)
    gemm_fp16<1><<<dim3(3 * DD / 128, (BB * SS) / 128), 256, SMEM_BYTES>>>(
        xh, w1h, bqkv, nullptr, BB * SS, 3 * DD, DD);

    // 3) routed attention (fp16 K/V gather, writes fp16 proj-A matrix)
    attn_k<<<BB * HH * (SS / 32), 256>>>(routes);

    // 4) out projection
    gemm_fp16<0><<<dim3(DD / 128, (BB * SS) / 128), 256, SMEM_BYTES>>>(
        ath, w2h, bout, out, BB * SS, DD, DD);
}